// round 5
// baseline (speedup 1.0000x reference)
#include <cuda_runtime.h>
#include <math.h>

#define R_TOT 2048   // B*C rows
#define N0 8192
#define M1 4099
#define M2 2053
#define M3 1030
#define M4 518
#define M1P 4100
#define M2P 2056
#define M3P 1032
#define M4P 520
#define CB 64
#define BB 32

__constant__ float c_dlo[8] = {-0.010597401784997278f, 0.032883011666982945f, 0.030841381835986965f,
                               -0.18703481171888114f, -0.02798376941698385f, 0.6308807679295904f,
                               0.7148465705525415f, 0.23037781330885523f};
__constant__ float c_dhi[8] = {-0.23037781330885523f, 0.7148465705525415f, -0.6308807679295904f,
                               -0.02798376941698385f, 0.18703481171888114f, 0.030841381835986965f,
                               -0.032883011666982945f, -0.010597401784997278f};

// Scratch (static device globals; allocation-free per harness rules)
__device__ __align__(256) float g_a1[(size_t)R_TOT * M1P];
__device__ __align__(256) float g_d1[(size_t)R_TOT * M1P];
__device__ __align__(256) float g_a2[(size_t)R_TOT * M2P];
__device__ __align__(256) float g_d2[(size_t)R_TOT * M2P];
__device__ __align__(256) float g_a3[(size_t)R_TOT * M3P];
__device__ __align__(256) float g_d3[(size_t)R_TOT * M3P];
__device__ __align__(256) float g_a4[(size_t)R_TOT * M4P];
__device__ __align__(256) float g_d4[(size_t)R_TOT * M4P];
__device__ __align__(256) float g_a4t[(size_t)M4 * R_TOT];    // [k][row]
__device__ __align__(256) float g_d4t[(size_t)M4 * R_TOT];
__device__ __align__(256) float g_a4mt[(size_t)M4 * R_TOT];   // mix out, [k][row]
__device__ __align__(256) float g_d4mt[(size_t)M4 * R_TOT];
__device__ __align__(256) float g_a4m[(size_t)R_TOT * M4P];   // [row][k]
__device__ __align__(256) float g_d4m[(size_t)R_TOT * M4P];
__device__ __align__(256) float g_wt1[(size_t)M4 * CB * CB];  // [k][i*64+o]
__device__ __align__(256) float g_wt2[(size_t)M4 * CB * CB];

// ---------------------------------------------------------------------------
// Combined forward transposes (z=0: a4->a4t, 1: d4->d4t, 2: w1->wt1, 3: w2->wt2)
// dst[c][r] = src[r][c]
// ---------------------------------------------------------------------------
__global__ void tr4_kernel(const float* __restrict__ s0, const float* __restrict__ s1,
                           const float* __restrict__ s2, const float* __restrict__ s3,
                           float* __restrict__ o0, float* __restrict__ o1,
                           float* __restrict__ o2, float* __restrict__ o3) {
    __shared__ float tile[32][33];
    int z = blockIdx.z;
    const float* __restrict__ src; float* __restrict__ dst; int R, ss, ds;
    if (z == 0)      { src = s0; dst = o0; R = R_TOT; ss = M4P; ds = R_TOT; }
    else if (z == 1) { src = s1; dst = o1; R = R_TOT; ss = M4P; ds = R_TOT; }
    else if (z == 2) { src = s2; dst = o2; R = 4096;  ss = M4;  ds = 4096; }
    else             { src = s3; dst = o3; R = 4096;  ss = M4;  ds = 4096; }
    int c0 = blockIdx.x * 32;
    int r0 = blockIdx.y * 32;
    if (r0 >= R) return;
    int tx = threadIdx.x, ty = threadIdx.y;
#pragma unroll
    for (int i = 0; i < 32; i += 8) {
        int r = r0 + ty + i, c = c0 + tx;
        if (r < R && c < M4) tile[ty + i][tx] = src[(size_t)r * ss + c];
    }
    __syncthreads();
#pragma unroll
    for (int i = 0; i < 32; i += 8) {
        int c = c0 + ty + i, r = r0 + tx;
        if (c < M4 && r < R) dst[(size_t)c * ds + r] = tile[tx][ty + i];
    }
}

// ---------------------------------------------------------------------------
// Back transposes (z=0: a4mt->a4m, 1: d4mt->d4m). src [M4][2048] -> dst [2048][M4P]
// ---------------------------------------------------------------------------
__global__ void tr2_kernel(const float* __restrict__ s0, const float* __restrict__ s1,
                           float* __restrict__ o0, float* __restrict__ o1) {
    __shared__ float tile[32][33];
    const float* __restrict__ src = blockIdx.z ? s1 : s0;
    float* __restrict__ dst = blockIdx.z ? o1 : o0;
    int c0 = blockIdx.x * 32;   // col in src (2048)
    int r0 = blockIdx.y * 32;   // row in src (518)
    int tx = threadIdx.x, ty = threadIdx.y;
#pragma unroll
    for (int i = 0; i < 32; i += 8) {
        int r = r0 + ty + i;
        if (r < M4) tile[ty + i][tx] = src[(size_t)r * R_TOT + c0 + tx];
    }
    __syncthreads();
#pragma unroll
    for (int i = 0; i < 32; i += 8) {
        int r = r0 + tx;
        if (r < M4) dst[(size_t)(c0 + ty + i) * M4P + r] = tile[tx][ty + i];
    }
}

// ---------------------------------------------------------------------------
// Fused transpose + DWT level 1: reads x (B,N,C) directly.
// ---------------------------------------------------------------------------
__global__ __launch_bounds__(256) void dwt1_kernel(const float* __restrict__ x,
                                                   float* __restrict__ a1,
                                                   float* __restrict__ d1) {
    __shared__ float xs[32][263];
    int k0 = blockIdx.x * 128;
    int ct = blockIdx.y;
    int b = ct >> 1;
    int c0 = (ct & 1) * 32;
    int n_start = 2 * k0 - 6;
    for (int idx = threadIdx.x; idx < 262 * 32; idx += 256) {
        int nn = idx >> 5, cc = idx & 31;
        int n = n_start + nn;
        n = (n < 0) ? (-1 - n) : n;
        n = (n >= N0) ? (2 * N0 - 1 - n) : n;
        xs[cc][nn] = __ldg(&x[((size_t)b * N0 + n) * CB + c0 + cc]);
    }
    __syncthreads();
#pragma unroll 4
    for (int s = 0; s < 16; s++) {
        int oi = s * 256 + threadIdx.x;
        int cc = oi >> 7, kk = oi & 127;
        int k = k0 + kk;
        if (k >= M1) continue;
        float sa = 0.f, sd = 0.f;
#pragma unroll
        for (int j = 0; j < 8; j++) {
            float v = xs[cc][2 * kk + 7 - j];
            sa = fmaf(v, c_dlo[j], sa);
            sd = fmaf(v, c_dhi[j], sd);
        }
        size_t off = (size_t)(b * 64 + c0 + cc) * M1P + k;
        a1[off] = sa;
        d1[off] = sd;
    }
}

// ---------------------------------------------------------------------------
// DWT level (2-4), vectorized: each thread computes 4 outputs k0..k0+3 via
// 4x LDG.128 covering x[8t-8 .. 8t+7], stores 2x STG.128.
// y[k] = sum_j filt[j] * x_sym[2k+1-j]
// ---------------------------------------------------------------------------
__global__ __launch_bounds__(256) void dwt_kernel(const float* __restrict__ in,
                                                  float* __restrict__ a, float* __restrict__ d,
                                                  int n, int m, int sIn, int sOut) {
    int row = blockIdx.y;
    int t = blockIdx.x * 256 + threadIdx.x;
    int k0 = 4 * t;
    if (k0 >= m) return;
    const float* __restrict__ x = in + (size_t)row * sIn;
    if (t >= 1 && k0 + 4 <= m && 8 * t + 7 < n) {
        const float4* __restrict__ x4 = reinterpret_cast<const float4*>(x);
        float4 v0 = __ldg(&x4[2 * t - 2]);
        float4 v1 = __ldg(&x4[2 * t - 1]);
        float4 v2 = __ldg(&x4[2 * t]);
        float4 v3 = __ldg(&x4[2 * t + 1]);
        float xv[16] = {v0.x, v0.y, v0.z, v0.w, v1.x, v1.y, v1.z, v1.w,
                        v2.x, v2.y, v2.z, v2.w, v3.x, v3.y, v3.z, v3.w};
        float sa[4] = {0.f, 0.f, 0.f, 0.f}, sd[4] = {0.f, 0.f, 0.f, 0.f};
#pragma unroll
        for (int u = 0; u < 4; u++) {
#pragma unroll
            for (int j = 0; j < 8; j++) {
                float v = xv[9 + 2 * u - j];
                sa[u] = fmaf(v, c_dlo[j], sa[u]);
                sd[u] = fmaf(v, c_dhi[j], sd[u]);
            }
        }
        size_t ob = (size_t)row * sOut + k0;
        *reinterpret_cast<float4*>(a + ob) = make_float4(sa[0], sa[1], sa[2], sa[3]);
        *reinterpret_cast<float4*>(d + ob) = make_float4(sd[0], sd[1], sd[2], sd[3]);
    } else {
        for (int u = 0; u < 4; u++) {
            int k = k0 + u;
            if (k >= m) break;
            int base = 2 * k + 1;
            float sa = 0.f, sd = 0.f;
#pragma unroll
            for (int j = 0; j < 8; j++) {
                int p = base - j;
                p = (p < 0) ? (-1 - p) : p;
                p = (p >= n) ? (2 * n - 1 - p) : p;
                float v = __ldg(&x[p]);
                sa = fmaf(v, c_dlo[j], sa);
                sd = fmaf(v, c_dhi[j], sd);
            }
            a[(size_t)row * sOut + k] = sa;
            d[(size_t)row * sOut + k] = sd;
        }
    }
}

// ---------------------------------------------------------------------------
// IDWT level, vectorized: thread t computes 8 outputs p=8t..8t+7 (pairs q=4t..4t+3)
// via 4x LDG.128 (A[4t..4t+7], D[4t..4t+7]), stores 2x STG.128.
// p even: taps filt[1+2s]; p odd: taps filt[2s]; r=p>>1, r+3 < m guaranteed.
// ---------------------------------------------------------------------------
__global__ __launch_bounds__(256) void idwt_kernel(const float* __restrict__ ca,
                                                   const float* __restrict__ cd,
                                                   float* __restrict__ out, int m, int out_len,
                                                   int sIn, int sOut) {
    int row = blockIdx.y;
    int t = blockIdx.x * 256 + threadIdx.x;
    int p0 = 8 * t;
    if (p0 >= out_len) return;
    const float* __restrict__ A = ca + (size_t)row * sIn;
    const float* __restrict__ D = cd + (size_t)row * sIn;
    if (p0 + 8 <= out_len) {
        const float4* __restrict__ A4 = reinterpret_cast<const float4*>(A);
        const float4* __restrict__ D4 = reinterpret_cast<const float4*>(D);
        float4 a0 = __ldg(&A4[t]), a1 = __ldg(&A4[t + 1]);
        float4 d0 = __ldg(&D4[t]), d1 = __ldg(&D4[t + 1]);
        float av[8] = {a0.x, a0.y, a0.z, a0.w, a1.x, a1.y, a1.z, a1.w};
        float dv[8] = {d0.x, d0.y, d0.z, d0.w, d1.x, d1.y, d1.z, d1.w};
        float e[4], o[4];
#pragma unroll
        for (int u = 0; u < 4; u++) {
            float se = 0.f, so = 0.f;
#pragma unroll
            for (int s = 0; s < 4; s++) {
                float a_ = av[u + s], d_ = dv[u + s];
                se = fmaf(a_, c_dlo[2 * s + 1], fmaf(d_, c_dhi[2 * s + 1], se));
                so = fmaf(a_, c_dlo[2 * s],     fmaf(d_, c_dhi[2 * s],     so));
            }
            e[u] = se; o[u] = so;
        }
        float* __restrict__ op = out + (size_t)row * sOut + p0;
        *reinterpret_cast<float4*>(op)     = make_float4(e[0], o[0], e[1], o[1]);
        *reinterpret_cast<float4*>(op + 4) = make_float4(e[2], o[2], e[3], o[3]);
    } else {
        for (int p = p0; p < out_len; p++) {
            int r = p >> 1;
            float s = 0.f;
            if (p & 1) {
#pragma unroll
                for (int u = 0; u < 4; u++)
                    s = fmaf(__ldg(&A[r + u]), c_dlo[2 * u], fmaf(__ldg(&D[r + u]), c_dhi[2 * u], s));
            } else {
#pragma unroll
                for (int u = 0; u < 4; u++)
                    s = fmaf(__ldg(&A[r + u]), c_dlo[2 * u + 1], fmaf(__ldg(&D[r + u]), c_dhi[2 * u + 1], s));
            }
            out[(size_t)row * sOut + p] = s;
        }
    }
}

// ---------------------------------------------------------------------------
// Channel mix (coalesced, vectorized loads): in [k][row], w [k][i*64+o],
// out [k][row] float4 stores. Conflict-free LDS mapping.
// ---------------------------------------------------------------------------
__global__ __launch_bounds__(256) void mix_kernel(
    const float* __restrict__ a4t, const float* __restrict__ d4t,
    const float* __restrict__ wt1, const float* __restrict__ wt2,
    float* __restrict__ a4mt, float* __restrict__ d4mt) {
    int k = blockIdx.x;
    const float* __restrict__ in = blockIdx.y ? d4t : a4t;
    const float* __restrict__ wt = blockIdx.y ? wt2 : wt1;
    float* __restrict__ out = blockIdx.y ? d4mt : a4mt;

    __shared__ __align__(16) float ws[4096];  // ws[i*64+o]
    __shared__ float as[32 * 65];             // as[b*65+i]
    int tid = threadIdx.x;
    const float4* __restrict__ wk4 = reinterpret_cast<const float4*>(wt + (size_t)k * 4096);
    const float4* __restrict__ ik4 = reinterpret_cast<const float4*>(in + (size_t)k * R_TOT);
    float4* ws4w = reinterpret_cast<float4*>(ws);
    for (int idx = tid; idx < 1024; idx += 256) ws4w[idx] = __ldg(&wk4[idx]);
    for (int idx = tid; idx < 512; idx += 256) {
        float4 v = __ldg(&ik4[idx]);
        int b = idx >> 4, i = (idx & 15) * 4;
        float* p = &as[b * 65 + i];
        p[0] = v.x; p[1] = v.y; p[2] = v.z; p[3] = v.w;
    }
    __syncthreads();

    int b = tid >> 3;
    int lg = tid & 7;
    const float4* ws4 = reinterpret_cast<const float4*>(ws);
    float4 acc0 = make_float4(0.f, 0.f, 0.f, 0.f);
    float4 acc1 = make_float4(0.f, 0.f, 0.f, 0.f);
#pragma unroll
    for (int i = 0; i < 64; i++) {
        float av = as[b * 65 + i];
        float4 w0 = ws4[i * 16 + lg];
        float4 w1 = ws4[i * 16 + 8 + lg];
        acc0.x = fmaf(av, w0.x, acc0.x); acc0.y = fmaf(av, w0.y, acc0.y);
        acc0.z = fmaf(av, w0.z, acc0.z); acc0.w = fmaf(av, w0.w, acc0.w);
        acc1.x = fmaf(av, w1.x, acc1.x); acc1.y = fmaf(av, w1.y, acc1.y);
        acc1.z = fmaf(av, w1.z, acc1.z); acc1.w = fmaf(av, w1.w, acc1.w);
    }
    float4* ok = reinterpret_cast<float4*>(out + (size_t)k * R_TOT + b * 64);
    ok[lg] = acc0;
    ok[8 + lg] = acc1;
}

// ---------------------------------------------------------------------------
// Fused IDWT level 1 + transpose-back + dense shortcut + mish.
// ---------------------------------------------------------------------------
__device__ __forceinline__ float mish_f(float v) {
    float sp = (v > 20.f) ? v : log1pf(expf(v));
    return v * tanhf(sp);
}

__global__ __launch_bounds__(256) void ifinal_kernel(
    const float* __restrict__ a1, const float* __restrict__ d1,
    const float* __restrict__ x, const float* __restrict__ dk,
    const float* __restrict__ bias, float* __restrict__ out) {
    int b = blockIdx.y;
    int n0 = blockIdx.x * 32;
    int r0 = n0 >> 1;
    __shared__ float sA[64][20];
    __shared__ float sD[64][20];
    __shared__ __align__(16) float dks[4096];
    __shared__ float xs[32 * 65];
    __shared__ float ys[32 * 65];
    __shared__ float bs[64];
    int tid = threadIdx.x;
    for (int idx = tid; idx < 4096; idx += 256) dks[idx] = __ldg(&dk[idx]);
    if (tid < 64) bs[tid] = __ldg(&bias[tid]);
    for (int idx = tid; idx < 64 * 19; idx += 256) {
        int c = idx / 19, i = idx - c * 19;
        size_t off = (size_t)(b * 64 + c) * M1P + r0 + i;
        sA[c][i] = __ldg(&a1[off]);
        sD[c][i] = __ldg(&d1[off]);
    }
    for (int idx = tid; idx < 2048; idx += 256) {
        int nn = idx >> 6, i = idx & 63;
        xs[nn * 65 + i] = __ldg(&x[((size_t)b * N0 + n0 + nn) * CB + i]);
    }
    __syncthreads();

#pragma unroll
    for (int s = 0; s < 8; s++) {
        int oi = s * 256 + tid;
        int c = oi >> 5, nn = oi & 31;
        int ri = nn >> 1;
        float sv = 0.f;
        if (nn & 1) {
#pragma unroll
            for (int t = 0; t < 4; t++)
                sv = fmaf(sA[c][ri + t], c_dlo[2 * t], fmaf(sD[c][ri + t], c_dhi[2 * t], sv));
        } else {
#pragma unroll
            for (int t = 0; t < 4; t++)
                sv = fmaf(sA[c][ri + t], c_dlo[2 * t + 1], fmaf(sD[c][ri + t], c_dhi[2 * t + 1], sv));
        }
        ys[nn * 65 + c] = sv;
    }
    __syncthreads();

    int nn = tid >> 3;
    int lg = tid & 7;
    int g = lg * 4;
    const float4* dk4 = reinterpret_cast<const float4*>(dks);
    float4 acc0 = make_float4(bs[g], bs[g + 1], bs[g + 2], bs[g + 3]);
    float4 acc1 = make_float4(bs[g + 32], bs[g + 33], bs[g + 34], bs[g + 35]);
#pragma unroll
    for (int i = 0; i < 64; i++) {
        float xv = xs[nn * 65 + i];
        float4 w0 = dk4[i * 16 + lg];
        float4 w1 = dk4[i * 16 + 8 + lg];
        acc0.x = fmaf(xv, w0.x, acc0.x); acc0.y = fmaf(xv, w0.y, acc0.y);
        acc0.z = fmaf(xv, w0.z, acc0.z); acc0.w = fmaf(xv, w0.w, acc0.w);
        acc1.x = fmaf(xv, w1.x, acc1.x); acc1.y = fmaf(xv, w1.y, acc1.y);
        acc1.z = fmaf(xv, w1.z, acc1.z); acc1.w = fmaf(xv, w1.w, acc1.w);
    }
    float v0[4] = {acc0.x, acc0.y, acc0.z, acc0.w};
    float v1[4] = {acc1.x, acc1.y, acc1.z, acc1.w};
#pragma unroll
    for (int u = 0; u < 4; u++) {
        v0[u] = mish_f(v0[u] + ys[nn * 65 + g + u]);
        v1[u] = mish_f(v1[u] + ys[nn * 65 + g + 32 + u]);
    }
    float4* op = reinterpret_cast<float4*>(&out[((size_t)b * N0 + n0 + nn) * CB]);
    op[lg] = make_float4(v0[0], v0[1], v0[2], v0[3]);
    op[8 + lg] = make_float4(v1[0], v1[1], v1[2], v1[3]);
}

// ---------------------------------------------------------------------------
extern "C" void kernel_launch(void* const* d_in, const int* in_sizes, int n_in,
                              void* d_out, int out_size) {
    (void)in_sizes; (void)n_in; (void)out_size;
    const float* x    = (const float*)d_in[0];
    const float* w1   = (const float*)d_in[1];
    const float* w2   = (const float*)d_in[2];
    const float* dk   = (const float*)d_in[3];
    const float* bias = (const float*)d_in[4];
    float* out = (float*)d_out;

    float *a1, *d1, *a2, *d2, *a3, *d3, *a4, *d4;
    float *a4t, *d4t, *a4mt, *d4mt, *a4m, *d4m, *wt1, *wt2;
    cudaGetSymbolAddress((void**)&a1,   g_a1);
    cudaGetSymbolAddress((void**)&d1,   g_d1);
    cudaGetSymbolAddress((void**)&a2,   g_a2);
    cudaGetSymbolAddress((void**)&d2,   g_d2);
    cudaGetSymbolAddress((void**)&a3,   g_a3);
    cudaGetSymbolAddress((void**)&d3,   g_d3);
    cudaGetSymbolAddress((void**)&a4,   g_a4);
    cudaGetSymbolAddress((void**)&d4,   g_d4);
    cudaGetSymbolAddress((void**)&a4t,  g_a4t);
    cudaGetSymbolAddress((void**)&d4t,  g_d4t);
    cudaGetSymbolAddress((void**)&a4mt, g_a4mt);
    cudaGetSymbolAddress((void**)&d4mt, g_d4mt);
    cudaGetSymbolAddress((void**)&a4m,  g_a4m);
    cudaGetSymbolAddress((void**)&d4m,  g_d4m);
    cudaGetSymbolAddress((void**)&wt1,  g_wt1);
    cudaGetSymbolAddress((void**)&wt2,  g_wt2);

    dim3 trb(32, 8);
    // 1. fused transpose + DWT L1
    dwt1_kernel<<<dim3((M1 + 127) / 128, BB * 2), 256>>>(x, a1, d1);
    // 2-4. DWT levels 2-4, vectorized (4 outputs/thread)
    dwt_kernel<<<dim3(((M2 + 3) / 4 + 255) / 256, R_TOT), 256>>>(a1, a2, d2, M1, M2, M1P, M2P);
    dwt_kernel<<<dim3(((M3 + 3) / 4 + 255) / 256, R_TOT), 256>>>(a2, a3, d3, M2, M3, M2P, M3P);
    dwt_kernel<<<dim3(((M4 + 3) / 4 + 255) / 256, R_TOT), 256>>>(a3, a4, d4, M3, M4, M3P, M4P);
    // 5. all forward transposes in one launch (a4,d4 -> k-major; w1,w2 -> k-major)
    tr4_kernel<<<dim3((M4 + 31) / 32, 4096 / 32, 4), trb>>>(a4, d4, w1, w2, a4t, d4t, wt1, wt2);
    // 6. channel mix
    mix_kernel<<<dim3(M4, 2), 256>>>(a4t, d4t, wt1, wt2, a4mt, d4mt);
    // 7. transpose mixed back to row-major
    tr2_kernel<<<dim3(R_TOT / 32, (M4 + 31) / 32, 2), trb>>>(a4mt, d4mt, a4m, d4m);
    // 8-10. IDWT levels 4->3->2->1, vectorized (8 outputs/thread)
    idwt_kernel<<<dim3(((M3 + 7) / 8 + 255) / 256, R_TOT), 256>>>(a4m, d4m, a3, M4, M3, M4P, M3P);
    idwt_kernel<<<dim3(((M2 + 7) / 8 + 255) / 256, R_TOT), 256>>>(a3, d3, a2, M3, M2, M3P, M2P);
    idwt_kernel<<<dim3(((M1 + 7) / 8 + 255) / 256, R_TOT), 256>>>(a2, d2, a1, M2, M1, M2P, M1P);
    // 11. fused IDWT L1 + transpose-back + dense shortcut + mish
    ifinal_kernel<<<dim3(N0 / 32, BB), 256>>>(a1, d1, x, dk, bias, out);
}

// round 6
// speedup vs baseline: 1.4975x; 1.4975x over previous
#include <cuda_runtime.h>
#include <math.h>

#define R_TOT 2048   // B*C rows
#define N0 8192
#define M1 4099
#define M2 2053
#define M3 1030
#define M4 518
#define M1P 4100
#define M2P 2056
#define M3P 1032
#define M4P 520
#define CB 64
#define BB 32

__constant__ float c_dlo[8] = {-0.010597401784997278f, 0.032883011666982945f, 0.030841381835986965f,
                               -0.18703481171888114f, -0.02798376941698385f, 0.6308807679295904f,
                               0.7148465705525415f, 0.23037781330885523f};
__constant__ float c_dhi[8] = {-0.23037781330885523f, 0.7148465705525415f, -0.6308807679295904f,
                               -0.02798376941698385f, 0.18703481171888114f, 0.030841381835986965f,
                               -0.032883011666982945f, -0.010597401784997278f};

// Scratch (static device globals; allocation-free per harness rules)
__device__ __align__(256) float g_a1[(size_t)R_TOT * M1P];
__device__ __align__(256) float g_d1[(size_t)R_TOT * M1P];
__device__ __align__(256) float g_a2[(size_t)R_TOT * M2P];
__device__ __align__(256) float g_d2[(size_t)R_TOT * M2P];
__device__ __align__(256) float g_a3[(size_t)R_TOT * M3P];
__device__ __align__(256) float g_d3[(size_t)R_TOT * M3P];
__device__ __align__(256) float g_a4[(size_t)R_TOT * M4P];
__device__ __align__(256) float g_d4[(size_t)R_TOT * M4P];
__device__ __align__(256) float g_a4t[(size_t)M4 * R_TOT];    // [k][row]
__device__ __align__(256) float g_d4t[(size_t)M4 * R_TOT];
__device__ __align__(256) float g_a4mt[(size_t)M4 * R_TOT];   // mix out, [k][row]
__device__ __align__(256) float g_d4mt[(size_t)M4 * R_TOT];
__device__ __align__(256) float g_a4m[(size_t)R_TOT * M4P];   // [row][k]
__device__ __align__(256) float g_d4m[(size_t)R_TOT * M4P];
__device__ __align__(256) float g_wt1[(size_t)M4 * CB * CB];  // [k][i*64+o]
__device__ __align__(256) float g_wt2[(size_t)M4 * CB * CB];

// ---------------------------------------------------------------------------
// Combined forward transposes (z=0: a4->a4t, 1: d4->d4t, 2: w1->wt1, 3: w2->wt2)
// dst[c][r] = src[r][c]
// ---------------------------------------------------------------------------
__global__ void tr4_kernel(const float* __restrict__ s0, const float* __restrict__ s1,
                           const float* __restrict__ s2, const float* __restrict__ s3,
                           float* __restrict__ o0, float* __restrict__ o1,
                           float* __restrict__ o2, float* __restrict__ o3) {
    __shared__ float tile[32][33];
    int z = blockIdx.z;
    const float* __restrict__ src; float* __restrict__ dst; int R, ss, ds;
    if (z == 0)      { src = s0; dst = o0; R = R_TOT; ss = M4P; ds = R_TOT; }
    else if (z == 1) { src = s1; dst = o1; R = R_TOT; ss = M4P; ds = R_TOT; }
    else if (z == 2) { src = s2; dst = o2; R = 4096;  ss = M4;  ds = 4096; }
    else             { src = s3; dst = o3; R = 4096;  ss = M4;  ds = 4096; }
    int c0 = blockIdx.x * 32;
    int r0 = blockIdx.y * 32;
    if (r0 >= R) return;
    int tx = threadIdx.x, ty = threadIdx.y;
#pragma unroll
    for (int i = 0; i < 32; i += 8) {
        int r = r0 + ty + i, c = c0 + tx;
        if (r < R && c < M4) tile[ty + i][tx] = src[(size_t)r * ss + c];
    }
    __syncthreads();
#pragma unroll
    for (int i = 0; i < 32; i += 8) {
        int c = c0 + ty + i, r = r0 + tx;
        if (c < M4 && r < R) dst[(size_t)c * ds + r] = tile[tx][ty + i];
    }
}

// ---------------------------------------------------------------------------
// Back transposes (z=0: a4mt->a4m, 1: d4mt->d4m). src [M4][2048] -> dst [2048][M4P]
// ---------------------------------------------------------------------------
__global__ void tr2_kernel(const float* __restrict__ s0, const float* __restrict__ s1,
                           float* __restrict__ o0, float* __restrict__ o1) {
    __shared__ float tile[32][33];
    const float* __restrict__ src = blockIdx.z ? s1 : s0;
    float* __restrict__ dst = blockIdx.z ? o1 : o0;
    int c0 = blockIdx.x * 32;   // col in src (2048)
    int r0 = blockIdx.y * 32;   // row in src (518)
    int tx = threadIdx.x, ty = threadIdx.y;
#pragma unroll
    for (int i = 0; i < 32; i += 8) {
        int r = r0 + ty + i;
        if (r < M4) tile[ty + i][tx] = src[(size_t)r * R_TOT + c0 + tx];
    }
    __syncthreads();
#pragma unroll
    for (int i = 0; i < 32; i += 8) {
        int r = r0 + tx;
        if (r < M4) dst[(size_t)(c0 + ty + i) * M4P + r] = tile[tx][ty + i];
    }
}

// ---------------------------------------------------------------------------
// Fused transpose + DWT level 1: reads x (B,N,C) directly.
// ---------------------------------------------------------------------------
__global__ __launch_bounds__(256) void dwt1_kernel(const float* __restrict__ x,
                                                   float* __restrict__ a1,
                                                   float* __restrict__ d1) {
    __shared__ float xs[32][263];
    int k0 = blockIdx.x * 128;
    int ct = blockIdx.y;
    int b = ct >> 1;
    int c0 = (ct & 1) * 32;
    int n_start = 2 * k0 - 6;
    for (int idx = threadIdx.x; idx < 262 * 32; idx += 256) {
        int nn = idx >> 5, cc = idx & 31;
        int n = n_start + nn;
        n = (n < 0) ? (-1 - n) : n;
        n = (n >= N0) ? (2 * N0 - 1 - n) : n;
        xs[cc][nn] = __ldg(&x[((size_t)b * N0 + n) * CB + c0 + cc]);
    }
    __syncthreads();
#pragma unroll 4
    for (int s = 0; s < 16; s++) {
        int oi = s * 256 + threadIdx.x;
        int cc = oi >> 7, kk = oi & 127;
        int k = k0 + kk;
        if (k >= M1) continue;
        float sa = 0.f, sd = 0.f;
#pragma unroll
        for (int j = 0; j < 8; j++) {
            float v = xs[cc][2 * kk + 7 - j];
            sa = fmaf(v, c_dlo[j], sa);
            sd = fmaf(v, c_dhi[j], sd);
        }
        size_t off = (size_t)(b * 64 + c0 + cc) * M1P + k;
        a1[off] = sa;
        d1[off] = sd;
    }
}

// ---------------------------------------------------------------------------
// DWT level (2-4), vectorized: each thread computes 4 outputs k0..k0+3 via
// 4x LDG.128 covering x[8t-8 .. 8t+7], stores 2x STG.128.
// y[k] = sum_j filt[j] * x_sym[2k+1-j]
// ---------------------------------------------------------------------------
__global__ __launch_bounds__(256) void dwt_kernel(const float* __restrict__ in,
                                                  float* __restrict__ a, float* __restrict__ d,
                                                  int n, int m, int sIn, int sOut) {
    int row = blockIdx.y;
    int t = blockIdx.x * 256 + threadIdx.x;
    int k0 = 4 * t;
    if (k0 >= m) return;
    const float* __restrict__ x = in + (size_t)row * sIn;
    if (t >= 1 && k0 + 4 <= m && 8 * t + 7 < n) {
        const float4* __restrict__ x4 = reinterpret_cast<const float4*>(x);
        float4 v0 = __ldg(&x4[2 * t - 2]);
        float4 v1 = __ldg(&x4[2 * t - 1]);
        float4 v2 = __ldg(&x4[2 * t]);
        float4 v3 = __ldg(&x4[2 * t + 1]);
        float xv[16] = {v0.x, v0.y, v0.z, v0.w, v1.x, v1.y, v1.z, v1.w,
                        v2.x, v2.y, v2.z, v2.w, v3.x, v3.y, v3.z, v3.w};
        float sa[4] = {0.f, 0.f, 0.f, 0.f}, sd[4] = {0.f, 0.f, 0.f, 0.f};
#pragma unroll
        for (int u = 0; u < 4; u++) {
#pragma unroll
            for (int j = 0; j < 8; j++) {
                float v = xv[9 + 2 * u - j];
                sa[u] = fmaf(v, c_dlo[j], sa[u]);
                sd[u] = fmaf(v, c_dhi[j], sd[u]);
            }
        }
        size_t ob = (size_t)row * sOut + k0;
        *reinterpret_cast<float4*>(a + ob) = make_float4(sa[0], sa[1], sa[2], sa[3]);
        *reinterpret_cast<float4*>(d + ob) = make_float4(sd[0], sd[1], sd[2], sd[3]);
    } else {
        for (int u = 0; u < 4; u++) {
            int k = k0 + u;
            if (k >= m) break;
            int base = 2 * k + 1;
            float sa = 0.f, sd = 0.f;
#pragma unroll
            for (int j = 0; j < 8; j++) {
                int p = base - j;
                p = (p < 0) ? (-1 - p) : p;
                p = (p >= n) ? (2 * n - 1 - p) : p;
                float v = __ldg(&x[p]);
                sa = fmaf(v, c_dlo[j], sa);
                sd = fmaf(v, c_dhi[j], sd);
            }
            a[(size_t)row * sOut + k] = sa;
            d[(size_t)row * sOut + k] = sd;
        }
    }
}

// ---------------------------------------------------------------------------
// IDWT level, vectorized: thread t computes 8 outputs p=8t..8t+7 (pairs q=4t..4t+3)
// via 4x LDG.128 (A[4t..4t+7], D[4t..4t+7]), stores 2x STG.128.
// p even: taps filt[1+2s]; p odd: taps filt[2s]; r=p>>1, r+3 < m guaranteed.
// ---------------------------------------------------------------------------
__global__ __launch_bounds__(256) void idwt_kernel(const float* __restrict__ ca,
                                                   const float* __restrict__ cd,
                                                   float* __restrict__ out, int m, int out_len,
                                                   int sIn, int sOut) {
    int row = blockIdx.y;
    int t = blockIdx.x * 256 + threadIdx.x;
    int p0 = 8 * t;
    if (p0 >= out_len) return;
    const float* __restrict__ A = ca + (size_t)row * sIn;
    const float* __restrict__ D = cd + (size_t)row * sIn;
    if (p0 + 8 <= out_len) {
        const float4* __restrict__ A4 = reinterpret_cast<const float4*>(A);
        const float4* __restrict__ D4 = reinterpret_cast<const float4*>(D);
        float4 a0 = __ldg(&A4[t]), a1 = __ldg(&A4[t + 1]);
        float4 d0 = __ldg(&D4[t]), d1 = __ldg(&D4[t + 1]);
        float av[8] = {a0.x, a0.y, a0.z, a0.w, a1.x, a1.y, a1.z, a1.w};
        float dv[8] = {d0.x, d0.y, d0.z, d0.w, d1.x, d1.y, d1.z, d1.w};
        float e[4], o[4];
#pragma unroll
        for (int u = 0; u < 4; u++) {
            float se = 0.f, so = 0.f;
#pragma unroll
            for (int s = 0; s < 4; s++) {
                float a_ = av[u + s], d_ = dv[u + s];
                se = fmaf(a_, c_dlo[2 * s + 1], fmaf(d_, c_dhi[2 * s + 1], se));
                so = fmaf(a_, c_dlo[2 * s],     fmaf(d_, c_dhi[2 * s],     so));
            }
            e[u] = se; o[u] = so;
        }
        float* __restrict__ op = out + (size_t)row * sOut + p0;
        *reinterpret_cast<float4*>(op)     = make_float4(e[0], o[0], e[1], o[1]);
        *reinterpret_cast<float4*>(op + 4) = make_float4(e[2], o[2], e[3], o[3]);
    } else {
        for (int p = p0; p < out_len; p++) {
            int r = p >> 1;
            float s = 0.f;
            if (p & 1) {
#pragma unroll
                for (int u = 0; u < 4; u++)
                    s = fmaf(__ldg(&A[r + u]), c_dlo[2 * u], fmaf(__ldg(&D[r + u]), c_dhi[2 * u], s));
            } else {
#pragma unroll
                for (int u = 0; u < 4; u++)
                    s = fmaf(__ldg(&A[r + u]), c_dlo[2 * u + 1], fmaf(__ldg(&D[r + u]), c_dhi[2 * u + 1], s));
            }
            out[(size_t)row * sOut + p] = s;
        }
    }
}

// ---------------------------------------------------------------------------
// Channel mix (coalesced, vectorized loads): in [k][row], w [k][i*64+o],
// out [k][row] float4 stores. Conflict-free LDS mapping.
// ---------------------------------------------------------------------------
__global__ __launch_bounds__(256) void mix_kernel(
    const float* __restrict__ a4t, const float* __restrict__ d4t,
    const float* __restrict__ wt1, const float* __restrict__ wt2,
    float* __restrict__ a4mt, float* __restrict__ d4mt) {
    int k = blockIdx.x;
    const float* __restrict__ in = blockIdx.y ? d4t : a4t;
    const float* __restrict__ wt = blockIdx.y ? wt2 : wt1;
    float* __restrict__ out = blockIdx.y ? d4mt : a4mt;

    __shared__ __align__(16) float ws[4096];  // ws[i*64+o]
    __shared__ float as[32 * 65];             // as[b*65+i]
    int tid = threadIdx.x;
    const float4* __restrict__ wk4 = reinterpret_cast<const float4*>(wt + (size_t)k * 4096);
    const float4* __restrict__ ik4 = reinterpret_cast<const float4*>(in + (size_t)k * R_TOT);
    float4* ws4w = reinterpret_cast<float4*>(ws);
    for (int idx = tid; idx < 1024; idx += 256) ws4w[idx] = __ldg(&wk4[idx]);
    for (int idx = tid; idx < 512; idx += 256) {
        float4 v = __ldg(&ik4[idx]);
        int b = idx >> 4, i = (idx & 15) * 4;
        float* p = &as[b * 65 + i];
        p[0] = v.x; p[1] = v.y; p[2] = v.z; p[3] = v.w;
    }
    __syncthreads();

    int b = tid >> 3;
    int lg = tid & 7;
    const float4* ws4 = reinterpret_cast<const float4*>(ws);
    float4 acc0 = make_float4(0.f, 0.f, 0.f, 0.f);
    float4 acc1 = make_float4(0.f, 0.f, 0.f, 0.f);
#pragma unroll
    for (int i = 0; i < 64; i++) {
        float av = as[b * 65 + i];
        float4 w0 = ws4[i * 16 + lg];
        float4 w1 = ws4[i * 16 + 8 + lg];
        acc0.x = fmaf(av, w0.x, acc0.x); acc0.y = fmaf(av, w0.y, acc0.y);
        acc0.z = fmaf(av, w0.z, acc0.z); acc0.w = fmaf(av, w0.w, acc0.w);
        acc1.x = fmaf(av, w1.x, acc1.x); acc1.y = fmaf(av, w1.y, acc1.y);
        acc1.z = fmaf(av, w1.z, acc1.z); acc1.w = fmaf(av, w1.w, acc1.w);
    }
    float4* ok = reinterpret_cast<float4*>(out + (size_t)k * R_TOT + b * 64);
    ok[lg] = acc0;
    ok[8 + lg] = acc1;
}

// ---------------------------------------------------------------------------
// Fused IDWT level 1 + transpose-back + dense shortcut + mish.
// ---------------------------------------------------------------------------
__device__ __forceinline__ float mish_f(float v) {
    float sp = (v > 20.f) ? v : log1pf(expf(v));
    return v * tanhf(sp);
}

__global__ __launch_bounds__(256) void ifinal_kernel(
    const float* __restrict__ a1, const float* __restrict__ d1,
    const float* __restrict__ x, const float* __restrict__ dk,
    const float* __restrict__ bias, float* __restrict__ out) {
    int b = blockIdx.y;
    int n0 = blockIdx.x * 32;
    int r0 = n0 >> 1;
    __shared__ float sA[64][20];
    __shared__ float sD[64][20];
    __shared__ __align__(16) float dks[4096];
    __shared__ float xs[32 * 65];
    __shared__ float ys[32 * 65];
    __shared__ float bs[64];
    int tid = threadIdx.x;
    for (int idx = tid; idx < 4096; idx += 256) dks[idx] = __ldg(&dk[idx]);
    if (tid < 64) bs[tid] = __ldg(&bias[tid]);
    for (int idx = tid; idx < 64 * 19; idx += 256) {
        int c = idx / 19, i = idx - c * 19;
        size_t off = (size_t)(b * 64 + c) * M1P + r0 + i;
        sA[c][i] = __ldg(&a1[off]);
        sD[c][i] = __ldg(&d1[off]);
    }
    for (int idx = tid; idx < 2048; idx += 256) {
        int nn = idx >> 6, i = idx & 63;
        xs[nn * 65 + i] = __ldg(&x[((size_t)b * N0 + n0 + nn) * CB + i]);
    }
    __syncthreads();

#pragma unroll
    for (int s = 0; s < 8; s++) {
        int oi = s * 256 + tid;
        int c = oi >> 5, nn = oi & 31;
        int ri = nn >> 1;
        float sv = 0.f;
        if (nn & 1) {
#pragma unroll
            for (int t = 0; t < 4; t++)
                sv = fmaf(sA[c][ri + t], c_dlo[2 * t], fmaf(sD[c][ri + t], c_dhi[2 * t], sv));
        } else {
#pragma unroll
            for (int t = 0; t < 4; t++)
                sv = fmaf(sA[c][ri + t], c_dlo[2 * t + 1], fmaf(sD[c][ri + t], c_dhi[2 * t + 1], sv));
        }
        ys[nn * 65 + c] = sv;
    }
    __syncthreads();

    int nn = tid >> 3;
    int lg = tid & 7;
    int g = lg * 4;
    const float4* dk4 = reinterpret_cast<const float4*>(dks);
    float4 acc0 = make_float4(bs[g], bs[g + 1], bs[g + 2], bs[g + 3]);
    float4 acc1 = make_float4(bs[g + 32], bs[g + 33], bs[g + 34], bs[g + 35]);
#pragma unroll
    for (int i = 0; i < 64; i++) {
        float xv = xs[nn * 65 + i];
        float4 w0 = dk4[i * 16 + lg];
        float4 w1 = dk4[i * 16 + 8 + lg];
        acc0.x = fmaf(xv, w0.x, acc0.x); acc0.y = fmaf(xv, w0.y, acc0.y);
        acc0.z = fmaf(xv, w0.z, acc0.z); acc0.w = fmaf(xv, w0.w, acc0.w);
        acc1.x = fmaf(xv, w1.x, acc1.x); acc1.y = fmaf(xv, w1.y, acc1.y);
        acc1.z = fmaf(xv, w1.z, acc1.z); acc1.w = fmaf(xv, w1.w, acc1.w);
    }
    float v0[4] = {acc0.x, acc0.y, acc0.z, acc0.w};
    float v1[4] = {acc1.x, acc1.y, acc1.z, acc1.w};
#pragma unroll
    for (int u = 0; u < 4; u++) {
        v0[u] = mish_f(v0[u] + ys[nn * 65 + g + u]);
        v1[u] = mish_f(v1[u] + ys[nn * 65 + g + 32 + u]);
    }
    float4* op = reinterpret_cast<float4*>(&out[((size_t)b * N0 + n0 + nn) * CB]);
    op[lg] = make_float4(v0[0], v0[1], v0[2], v0[3]);
    op[8 + lg] = make_float4(v1[0], v1[1], v1[2], v1[3]);
}

// ---------------------------------------------------------------------------
extern "C" void kernel_launch(void* const* d_in, const int* in_sizes, int n_in,
                              void* d_out, int out_size) {
    (void)in_sizes; (void)n_in; (void)out_size;
    const float* x    = (const float*)d_in[0];
    const float* w1   = (const float*)d_in[1];
    const float* w2   = (const float*)d_in[2];
    const float* dk   = (const float*)d_in[3];
    const float* bias = (const float*)d_in[4];
    float* out = (float*)d_out;

    float *a1, *d1, *a2, *d2, *a3, *d3, *a4, *d4;
    float *a4t, *d4t, *a4mt, *d4mt, *a4m, *d4m, *wt1, *wt2;
    cudaGetSymbolAddress((void**)&a1,   g_a1);
    cudaGetSymbolAddress((void**)&d1,   g_d1);
    cudaGetSymbolAddress((void**)&a2,   g_a2);
    cudaGetSymbolAddress((void**)&d2,   g_d2);
    cudaGetSymbolAddress((void**)&a3,   g_a3);
    cudaGetSymbolAddress((void**)&d3,   g_d3);
    cudaGetSymbolAddress((void**)&a4,   g_a4);
    cudaGetSymbolAddress((void**)&d4,   g_d4);
    cudaGetSymbolAddress((void**)&a4t,  g_a4t);
    cudaGetSymbolAddress((void**)&d4t,  g_d4t);
    cudaGetSymbolAddress((void**)&a4mt, g_a4mt);
    cudaGetSymbolAddress((void**)&d4mt, g_d4mt);
    cudaGetSymbolAddress((void**)&a4m,  g_a4m);
    cudaGetSymbolAddress((void**)&d4m,  g_d4m);
    cudaGetSymbolAddress((void**)&wt1,  g_wt1);
    cudaGetSymbolAddress((void**)&wt2,  g_wt2);

    dim3 trb(32, 8);
    // 1. fused transpose + DWT L1
    dwt1_kernel<<<dim3((M1 + 127) / 128, BB * 2), 256>>>(x, a1, d1);
    // 2-4. DWT levels 2-4, vectorized (4 outputs/thread)
    dwt_kernel<<<dim3(((M2 + 3) / 4 + 255) / 256, R_TOT), 256>>>(a1, a2, d2, M1, M2, M1P, M2P);
    dwt_kernel<<<dim3(((M3 + 3) / 4 + 255) / 256, R_TOT), 256>>>(a2, a3, d3, M2, M3, M2P, M3P);
    dwt_kernel<<<dim3(((M4 + 3) / 4 + 255) / 256, R_TOT), 256>>>(a3, a4, d4, M3, M4, M3P, M4P);
    // 5. all forward transposes in one launch (a4,d4 -> k-major; w1,w2 -> k-major)
    tr4_kernel<<<dim3((M4 + 31) / 32, 4096 / 32, 4), trb>>>(a4, d4, w1, w2, a4t, d4t, wt1, wt2);
    // 6. channel mix
    mix_kernel<<<dim3(M4, 2), 256>>>(a4t, d4t, wt1, wt2, a4mt, d4mt);
    // 7. transpose mixed back to row-major
    tr2_kernel<<<dim3(R_TOT / 32, (M4 + 31) / 32, 2), trb>>>(a4mt, d4mt, a4m, d4m);
    // 8-10. IDWT levels 4->3->2->1, vectorized (8 outputs/thread)
    idwt_kernel<<<dim3(((M3 + 7) / 8 + 255) / 256, R_TOT), 256>>>(a4m, d4m, a3, M4, M3, M4P, M3P);
    idwt_kernel<<<dim3(((M2 + 7) / 8 + 255) / 256, R_TOT), 256>>>(a3, d3, a2, M3, M2, M3P, M2P);
    idwt_kernel<<<dim3(((M1 + 7) / 8 + 255) / 256, R_TOT), 256>>>(a2, d2, a1, M2, M1, M2P, M1P);
    // 11. fused IDWT L1 + transpose-back + dense shortcut + mish
    ifinal_kernel<<<dim3(N0 / 32, BB), 256>>>(a1, d1, x, dk, bias, out);
}

// round 7
// speedup vs baseline: 1.5035x; 1.0040x over previous
#include <cuda_runtime.h>
#include <math.h>

#define R_TOT 2048   // B*C rows
#define N0 8192
#define M1 4099
#define M2 2053
#define M3 1030
#define M4 518
#define M1P 4100
#define M2P 2056
#define M3P 1032
#define M4P 520
#define CB 64
#define BB 32

__constant__ float c_dlo[8] = {-0.010597401784997278f, 0.032883011666982945f, 0.030841381835986965f,
                               -0.18703481171888114f, -0.02798376941698385f, 0.6308807679295904f,
                               0.7148465705525415f, 0.23037781330885523f};
__constant__ float c_dhi[8] = {-0.23037781330885523f, 0.7148465705525415f, -0.6308807679295904f,
                               -0.02798376941698385f, 0.18703481171888114f, 0.030841381835986965f,
                               -0.032883011666982945f, -0.010597401784997278f};

// Scratch (static device globals; allocation-free per harness rules)
__device__ __align__(256) float g_a1[(size_t)R_TOT * M1P];
__device__ __align__(256) float g_d1[(size_t)R_TOT * M1P];
__device__ __align__(256) float g_a2[(size_t)R_TOT * M2P];
__device__ __align__(256) float g_d2[(size_t)R_TOT * M2P];
__device__ __align__(256) float g_a3[(size_t)R_TOT * M3P];
__device__ __align__(256) float g_d3[(size_t)R_TOT * M3P];
__device__ __align__(256) float g_a4[(size_t)R_TOT * M4P];
__device__ __align__(256) float g_d4[(size_t)R_TOT * M4P];
__device__ __align__(256) float g_a4t[(size_t)M4 * R_TOT];    // [k][row]
__device__ __align__(256) float g_d4t[(size_t)M4 * R_TOT];
__device__ __align__(256) float g_a4mt[(size_t)M4 * R_TOT];   // mix out, [k][row]
__device__ __align__(256) float g_d4mt[(size_t)M4 * R_TOT];
__device__ __align__(256) float g_a4m[(size_t)R_TOT * M4P];   // [row][k]
__device__ __align__(256) float g_d4m[(size_t)R_TOT * M4P];
__device__ __align__(256) float g_wt1[(size_t)M4 * CB * CB];  // [k][i*64+o]
__device__ __align__(256) float g_wt2[(size_t)M4 * CB * CB];

// ---------------------------------------------------------------------------
// Combined forward transposes (z=0: a4->a4t, 1: d4->d4t, 2: w1->wt1, 3: w2->wt2)
// dst[c][r] = src[r][c]
// ---------------------------------------------------------------------------
__global__ void tr4_kernel(const float* __restrict__ s0, const float* __restrict__ s1,
                           const float* __restrict__ s2, const float* __restrict__ s3,
                           float* __restrict__ o0, float* __restrict__ o1,
                           float* __restrict__ o2, float* __restrict__ o3) {
    __shared__ float tile[32][33];
    int z = blockIdx.z;
    const float* __restrict__ src; float* __restrict__ dst; int R, ss, ds;
    if (z == 0)      { src = s0; dst = o0; R = R_TOT; ss = M4P; ds = R_TOT; }
    else if (z == 1) { src = s1; dst = o1; R = R_TOT; ss = M4P; ds = R_TOT; }
    else if (z == 2) { src = s2; dst = o2; R = 4096;  ss = M4;  ds = 4096; }
    else             { src = s3; dst = o3; R = 4096;  ss = M4;  ds = 4096; }
    int c0 = blockIdx.x * 32;
    int r0 = blockIdx.y * 32;
    if (r0 >= R) return;
    int tx = threadIdx.x, ty = threadIdx.y;
#pragma unroll
    for (int i = 0; i < 32; i += 8) {
        int r = r0 + ty + i, c = c0 + tx;
        if (r < R && c < M4) tile[ty + i][tx] = src[(size_t)r * ss + c];
    }
    __syncthreads();
#pragma unroll
    for (int i = 0; i < 32; i += 8) {
        int c = c0 + ty + i, r = r0 + tx;
        if (c < M4 && r < R) dst[(size_t)c * ds + r] = tile[tx][ty + i];
    }
}

// ---------------------------------------------------------------------------
// Back transposes (z=0: a4mt->a4m, 1: d4mt->d4m). src [M4][2048] -> dst [2048][M4P]
// ---------------------------------------------------------------------------
__global__ void tr2_kernel(const float* __restrict__ s0, const float* __restrict__ s1,
                           float* __restrict__ o0, float* __restrict__ o1) {
    __shared__ float tile[32][33];
    const float* __restrict__ src = blockIdx.z ? s1 : s0;
    float* __restrict__ dst = blockIdx.z ? o1 : o0;
    int c0 = blockIdx.x * 32;   // col in src (2048)
    int r0 = blockIdx.y * 32;   // row in src (518)
    int tx = threadIdx.x, ty = threadIdx.y;
#pragma unroll
    for (int i = 0; i < 32; i += 8) {
        int r = r0 + ty + i;
        if (r < M4) tile[ty + i][tx] = src[(size_t)r * R_TOT + c0 + tx];
    }
    __syncthreads();
#pragma unroll
    for (int i = 0; i < 32; i += 8) {
        int r = r0 + tx;
        if (r < M4) dst[(size_t)(c0 + ty + i) * M4P + r] = tile[tx][ty + i];
    }
}

// ---------------------------------------------------------------------------
// Fused transpose + DWT level 1: reads x (B,N,C) directly.
// ---------------------------------------------------------------------------
__global__ __launch_bounds__(256) void dwt1_kernel(const float* __restrict__ x,
                                                   float* __restrict__ a1,
                                                   float* __restrict__ d1) {
    __shared__ float xs[32][263];
    int k0 = blockIdx.x * 128;
    int ct = blockIdx.y;
    int b = ct >> 1;
    int c0 = (ct & 1) * 32;
    int n_start = 2 * k0 - 6;
    for (int idx = threadIdx.x; idx < 262 * 32; idx += 256) {
        int nn = idx >> 5, cc = idx & 31;
        int n = n_start + nn;
        n = (n < 0) ? (-1 - n) : n;
        n = (n >= N0) ? (2 * N0 - 1 - n) : n;
        xs[cc][nn] = __ldg(&x[((size_t)b * N0 + n) * CB + c0 + cc]);
    }
    __syncthreads();
#pragma unroll 4
    for (int s = 0; s < 16; s++) {
        int oi = s * 256 + threadIdx.x;
        int cc = oi >> 7, kk = oi & 127;
        int k = k0 + kk;
        if (k >= M1) continue;
        float sa = 0.f, sd = 0.f;
#pragma unroll
        for (int j = 0; j < 8; j++) {
            float v = xs[cc][2 * kk + 7 - j];
            sa = fmaf(v, c_dlo[j], sa);
            sd = fmaf(v, c_dhi[j], sd);
        }
        size_t off = (size_t)(b * 64 + c0 + cc) * M1P + k;
        a1[off] = sa;
        d1[off] = sd;
    }
}

// ---------------------------------------------------------------------------
// DWT level (2-4), vectorized: each thread computes 4 outputs k0..k0+3 via
// 4x LDG.128 covering x[8t-8 .. 8t+7], stores 2x STG.128.
// y[k] = sum_j filt[j] * x_sym[2k+1-j]
// ---------------------------------------------------------------------------
__global__ __launch_bounds__(256) void dwt_kernel(const float* __restrict__ in,
                                                  float* __restrict__ a, float* __restrict__ d,
                                                  int n, int m, int sIn, int sOut) {
    int row = blockIdx.y;
    int t = blockIdx.x * 256 + threadIdx.x;
    int k0 = 4 * t;
    if (k0 >= m) return;
    const float* __restrict__ x = in + (size_t)row * sIn;
    if (t >= 1 && k0 + 4 <= m && 8 * t + 7 < n) {
        const float4* __restrict__ x4 = reinterpret_cast<const float4*>(x);
        float4 v0 = __ldg(&x4[2 * t - 2]);
        float4 v1 = __ldg(&x4[2 * t - 1]);
        float4 v2 = __ldg(&x4[2 * t]);
        float4 v3 = __ldg(&x4[2 * t + 1]);
        float xv[16] = {v0.x, v0.y, v0.z, v0.w, v1.x, v1.y, v1.z, v1.w,
                        v2.x, v2.y, v2.z, v2.w, v3.x, v3.y, v3.z, v3.w};
        float sa[4] = {0.f, 0.f, 0.f, 0.f}, sd[4] = {0.f, 0.f, 0.f, 0.f};
#pragma unroll
        for (int u = 0; u < 4; u++) {
#pragma unroll
            for (int j = 0; j < 8; j++) {
                float v = xv[9 + 2 * u - j];
                sa[u] = fmaf(v, c_dlo[j], sa[u]);
                sd[u] = fmaf(v, c_dhi[j], sd[u]);
            }
        }
        size_t ob = (size_t)row * sOut + k0;
        *reinterpret_cast<float4*>(a + ob) = make_float4(sa[0], sa[1], sa[2], sa[3]);
        *reinterpret_cast<float4*>(d + ob) = make_float4(sd[0], sd[1], sd[2], sd[3]);
    } else {
        for (int u = 0; u < 4; u++) {
            int k = k0 + u;
            if (k >= m) break;
            int base = 2 * k + 1;
            float sa = 0.f, sd = 0.f;
#pragma unroll
            for (int j = 0; j < 8; j++) {
                int p = base - j;
                p = (p < 0) ? (-1 - p) : p;
                p = (p >= n) ? (2 * n - 1 - p) : p;
                float v = __ldg(&x[p]);
                sa = fmaf(v, c_dlo[j], sa);
                sd = fmaf(v, c_dhi[j], sd);
            }
            a[(size_t)row * sOut + k] = sa;
            d[(size_t)row * sOut + k] = sd;
        }
    }
}

// ---------------------------------------------------------------------------
// IDWT level, vectorized: thread t computes 8 outputs p=8t..8t+7 (pairs q=4t..4t+3)
// via 4x LDG.128 (A[4t..4t+7], D[4t..4t+7]), stores 2x STG.128.
// p even: taps filt[1+2s]; p odd: taps filt[2s]; r=p>>1, r+3 < m guaranteed.
// ---------------------------------------------------------------------------
__global__ __launch_bounds__(256) void idwt_kernel(const float* __restrict__ ca,
                                                   const float* __restrict__ cd,
                                                   float* __restrict__ out, int m, int out_len,
                                                   int sIn, int sOut) {
    int row = blockIdx.y;
    int t = blockIdx.x * 256 + threadIdx.x;
    int p0 = 8 * t;
    if (p0 >= out_len) return;
    const float* __restrict__ A = ca + (size_t)row * sIn;
    const float* __restrict__ D = cd + (size_t)row * sIn;
    if (p0 + 8 <= out_len) {
        const float4* __restrict__ A4 = reinterpret_cast<const float4*>(A);
        const float4* __restrict__ D4 = reinterpret_cast<const float4*>(D);
        float4 a0 = __ldg(&A4[t]), a1 = __ldg(&A4[t + 1]);
        float4 d0 = __ldg(&D4[t]), d1 = __ldg(&D4[t + 1]);
        float av[8] = {a0.x, a0.y, a0.z, a0.w, a1.x, a1.y, a1.z, a1.w};
        float dv[8] = {d0.x, d0.y, d0.z, d0.w, d1.x, d1.y, d1.z, d1.w};
        float e[4], o[4];
#pragma unroll
        for (int u = 0; u < 4; u++) {
            float se = 0.f, so = 0.f;
#pragma unroll
            for (int s = 0; s < 4; s++) {
                float a_ = av[u + s], d_ = dv[u + s];
                se = fmaf(a_, c_dlo[2 * s + 1], fmaf(d_, c_dhi[2 * s + 1], se));
                so = fmaf(a_, c_dlo[2 * s],     fmaf(d_, c_dhi[2 * s],     so));
            }
            e[u] = se; o[u] = so;
        }
        float* __restrict__ op = out + (size_t)row * sOut + p0;
        *reinterpret_cast<float4*>(op)     = make_float4(e[0], o[0], e[1], o[1]);
        *reinterpret_cast<float4*>(op + 4) = make_float4(e[2], o[2], e[3], o[3]);
    } else {
        for (int p = p0; p < out_len; p++) {
            int r = p >> 1;
            float s = 0.f;
            if (p & 1) {
#pragma unroll
                for (int u = 0; u < 4; u++)
                    s = fmaf(__ldg(&A[r + u]), c_dlo[2 * u], fmaf(__ldg(&D[r + u]), c_dhi[2 * u], s));
            } else {
#pragma unroll
                for (int u = 0; u < 4; u++)
                    s = fmaf(__ldg(&A[r + u]), c_dlo[2 * u + 1], fmaf(__ldg(&D[r + u]), c_dhi[2 * u + 1], s));
            }
            out[(size_t)row * sOut + p] = s;
        }
    }
}

// ---------------------------------------------------------------------------
// Channel mix (coalesced, vectorized loads): in [k][row], w [k][i*64+o],
// out [k][row] float4 stores. Conflict-free LDS mapping.
// ---------------------------------------------------------------------------
__global__ __launch_bounds__(256) void mix_kernel(
    const float* __restrict__ a4t, const float* __restrict__ d4t,
    const float* __restrict__ wt1, const float* __restrict__ wt2,
    float* __restrict__ a4mt, float* __restrict__ d4mt) {
    int k = blockIdx.x;
    const float* __restrict__ in = blockIdx.y ? d4t : a4t;
    const float* __restrict__ wt = blockIdx.y ? wt2 : wt1;
    float* __restrict__ out = blockIdx.y ? d4mt : a4mt;

    __shared__ __align__(16) float ws[4096];  // ws[i*64+o]
    __shared__ float as[32 * 65];             // as[b*65+i]
    int tid = threadIdx.x;
    const float4* __restrict__ wk4 = reinterpret_cast<const float4*>(wt + (size_t)k * 4096);
    const float4* __restrict__ ik4 = reinterpret_cast<const float4*>(in + (size_t)k * R_TOT);
    float4* ws4w = reinterpret_cast<float4*>(ws);
    for (int idx = tid; idx < 1024; idx += 256) ws4w[idx] = __ldg(&wk4[idx]);
    for (int idx = tid; idx < 512; idx += 256) {
        float4 v = __ldg(&ik4[idx]);
        int b = idx >> 4, i = (idx & 15) * 4;
        float* p = &as[b * 65 + i];
        p[0] = v.x; p[1] = v.y; p[2] = v.z; p[3] = v.w;
    }
    __syncthreads();

    int b = tid >> 3;
    int lg = tid & 7;
    const float4* ws4 = reinterpret_cast<const float4*>(ws);
    float4 acc0 = make_float4(0.f, 0.f, 0.f, 0.f);
    float4 acc1 = make_float4(0.f, 0.f, 0.f, 0.f);
#pragma unroll
    for (int i = 0; i < 64; i++) {
        float av = as[b * 65 + i];
        float4 w0 = ws4[i * 16 + lg];
        float4 w1 = ws4[i * 16 + 8 + lg];
        acc0.x = fmaf(av, w0.x, acc0.x); acc0.y = fmaf(av, w0.y, acc0.y);
        acc0.z = fmaf(av, w0.z, acc0.z); acc0.w = fmaf(av, w0.w, acc0.w);
        acc1.x = fmaf(av, w1.x, acc1.x); acc1.y = fmaf(av, w1.y, acc1.y);
        acc1.z = fmaf(av, w1.z, acc1.z); acc1.w = fmaf(av, w1.w, acc1.w);
    }
    float4* ok = reinterpret_cast<float4*>(out + (size_t)k * R_TOT + b * 64);
    ok[lg] = acc0;
    ok[8 + lg] = acc1;
}

// ---------------------------------------------------------------------------
// Fused IDWT level 1 + transpose-back + dense shortcut + mish.
// ---------------------------------------------------------------------------
__device__ __forceinline__ float mish_f(float v) {
    float sp = (v > 20.f) ? v : log1pf(expf(v));
    return v * tanhf(sp);
}

__global__ __launch_bounds__(256) void ifinal_kernel(
    const float* __restrict__ a1, const float* __restrict__ d1,
    const float* __restrict__ x, const float* __restrict__ dk,
    const float* __restrict__ bias, float* __restrict__ out) {
    int b = blockIdx.y;
    int n0 = blockIdx.x * 32;
    int r0 = n0 >> 1;
    __shared__ float sA[64][20];
    __shared__ float sD[64][20];
    __shared__ __align__(16) float dks[4096];
    __shared__ float xs[32 * 65];
    __shared__ float ys[32 * 65];
    __shared__ float bs[64];
    int tid = threadIdx.x;
    for (int idx = tid; idx < 4096; idx += 256) dks[idx] = __ldg(&dk[idx]);
    if (tid < 64) bs[tid] = __ldg(&bias[tid]);
    for (int idx = tid; idx < 64 * 19; idx += 256) {
        int c = idx / 19, i = idx - c * 19;
        size_t off = (size_t)(b * 64 + c) * M1P + r0 + i;
        sA[c][i] = __ldg(&a1[off]);
        sD[c][i] = __ldg(&d1[off]);
    }
    for (int idx = tid; idx < 2048; idx += 256) {
        int nn = idx >> 6, i = idx & 63;
        xs[nn * 65 + i] = __ldg(&x[((size_t)b * N0 + n0 + nn) * CB + i]);
    }
    __syncthreads();

#pragma unroll
    for (int s = 0; s < 8; s++) {
        int oi = s * 256 + tid;
        int c = oi >> 5, nn = oi & 31;
        int ri = nn >> 1;
        float sv = 0.f;
        if (nn & 1) {
#pragma unroll
            for (int t = 0; t < 4; t++)
                sv = fmaf(sA[c][ri + t], c_dlo[2 * t], fmaf(sD[c][ri + t], c_dhi[2 * t], sv));
        } else {
#pragma unroll
            for (int t = 0; t < 4; t++)
                sv = fmaf(sA[c][ri + t], c_dlo[2 * t + 1], fmaf(sD[c][ri + t], c_dhi[2 * t + 1], sv));
        }
        ys[nn * 65 + c] = sv;
    }
    __syncthreads();

    int nn = tid >> 3;
    int lg = tid & 7;
    int g = lg * 4;
    const float4* dk4 = reinterpret_cast<const float4*>(dks);
    float4 acc0 = make_float4(bs[g], bs[g + 1], bs[g + 2], bs[g + 3]);
    float4 acc1 = make_float4(bs[g + 32], bs[g + 33], bs[g + 34], bs[g + 35]);
#pragma unroll
    for (int i = 0; i < 64; i++) {
        float xv = xs[nn * 65 + i];
        float4 w0 = dk4[i * 16 + lg];
        float4 w1 = dk4[i * 16 + 8 + lg];
        acc0.x = fmaf(xv, w0.x, acc0.x); acc0.y = fmaf(xv, w0.y, acc0.y);
        acc0.z = fmaf(xv, w0.z, acc0.z); acc0.w = fmaf(xv, w0.w, acc0.w);
        acc1.x = fmaf(xv, w1.x, acc1.x); acc1.y = fmaf(xv, w1.y, acc1.y);
        acc1.z = fmaf(xv, w1.z, acc1.z); acc1.w = fmaf(xv, w1.w, acc1.w);
    }
    float v0[4] = {acc0.x, acc0.y, acc0.z, acc0.w};
    float v1[4] = {acc1.x, acc1.y, acc1.z, acc1.w};
#pragma unroll
    for (int u = 0; u < 4; u++) {
        v0[u] = mish_f(v0[u] + ys[nn * 65 + g + u]);
        v1[u] = mish_f(v1[u] + ys[nn * 65 + g + 32 + u]);
    }
    float4* op = reinterpret_cast<float4*>(&out[((size_t)b * N0 + n0 + nn) * CB]);
    op[lg] = make_float4(v0[0], v0[1], v0[2], v0[3]);
    op[8 + lg] = make_float4(v1[0], v1[1], v1[2], v1[3]);
}

// ---------------------------------------------------------------------------
extern "C" void kernel_launch(void* const* d_in, const int* in_sizes, int n_in,
                              void* d_out, int out_size) {
    (void)in_sizes; (void)n_in; (void)out_size;
    const float* x    = (const float*)d_in[0];
    const float* w1   = (const float*)d_in[1];
    const float* w2   = (const float*)d_in[2];
    const float* dk   = (const float*)d_in[3];
    const float* bias = (const float*)d_in[4];
    float* out = (float*)d_out;

    float *a1, *d1, *a2, *d2, *a3, *d3, *a4, *d4;
    float *a4t, *d4t, *a4mt, *d4mt, *a4m, *d4m, *wt1, *wt2;
    cudaGetSymbolAddress((void**)&a1,   g_a1);
    cudaGetSymbolAddress((void**)&d1,   g_d1);
    cudaGetSymbolAddress((void**)&a2,   g_a2);
    cudaGetSymbolAddress((void**)&d2,   g_d2);
    cudaGetSymbolAddress((void**)&a3,   g_a3);
    cudaGetSymbolAddress((void**)&d3,   g_d3);
    cudaGetSymbolAddress((void**)&a4,   g_a4);
    cudaGetSymbolAddress((void**)&d4,   g_d4);
    cudaGetSymbolAddress((void**)&a4t,  g_a4t);
    cudaGetSymbolAddress((void**)&d4t,  g_d4t);
    cudaGetSymbolAddress((void**)&a4mt, g_a4mt);
    cudaGetSymbolAddress((void**)&d4mt, g_d4mt);
    cudaGetSymbolAddress((void**)&a4m,  g_a4m);
    cudaGetSymbolAddress((void**)&d4m,  g_d4m);
    cudaGetSymbolAddress((void**)&wt1,  g_wt1);
    cudaGetSymbolAddress((void**)&wt2,  g_wt2);

    dim3 trb(32, 8);
    // 1. fused transpose + DWT L1
    dwt1_kernel<<<dim3((M1 + 127) / 128, BB * 2), 256>>>(x, a1, d1);
    // 2-4. DWT levels 2-4, vectorized (4 outputs/thread)
    dwt_kernel<<<dim3(((M2 + 3) / 4 + 255) / 256, R_TOT), 256>>>(a1, a2, d2, M1, M2, M1P, M2P);
    dwt_kernel<<<dim3(((M3 + 3) / 4 + 255) / 256, R_TOT), 256>>>(a2, a3, d3, M2, M3, M2P, M3P);
    dwt_kernel<<<dim3(((M4 + 3) / 4 + 255) / 256, R_TOT), 256>>>(a3, a4, d4, M3, M4, M3P, M4P);
    // 5. all forward transposes in one launch (a4,d4 -> k-major; w1,w2 -> k-major)
    tr4_kernel<<<dim3((M4 + 31) / 32, 4096 / 32, 4), trb>>>(a4, d4, w1, w2, a4t, d4t, wt1, wt2);
    // 6. channel mix
    mix_kernel<<<dim3(M4, 2), 256>>>(a4t, d4t, wt1, wt2, a4mt, d4mt);
    // 7. transpose mixed back to row-major
    tr2_kernel<<<dim3(R_TOT / 32, (M4 + 31) / 32, 2), trb>>>(a4mt, d4mt, a4m, d4m);
    // 8-10. IDWT levels 4->3->2->1, vectorized (8 outputs/thread)
    idwt_kernel<<<dim3(((M3 + 7) / 8 + 255) / 256, R_TOT), 256>>>(a4m, d4m, a3, M4, M3, M4P, M3P);
    idwt_kernel<<<dim3(((M2 + 7) / 8 + 255) / 256, R_TOT), 256>>>(a3, d3, a2, M3, M2, M3P, M2P);
    idwt_kernel<<<dim3(((M1 + 7) / 8 + 255) / 256, R_TOT), 256>>>(a2, d2, a1, M2, M1, M2P, M1P);
    // 11. fused IDWT L1 + transpose-back + dense shortcut + mish
    ifinal_kernel<<<dim3(N0 / 32, BB), 256>>>(a1, d1, x, dk, bias, out);
}